// round 3
// baseline (speedup 1.0000x reference)
#include <cuda_runtime.h>

#define TT   256
#define HH   30
#define INP  3
#define NB   8            // batch elements per warp
#define WPB  7            // warps per block -> 147 blocks, <=7 warps/SM, one balanced wave

typedef unsigned long long ull;

// ---- f32x2 packed helpers (sm_103a) ----
__device__ __forceinline__ ull fma2(ull a, ull b, ull c) {
    ull d; asm("fma.rn.f32x2 %0,%1,%2,%3;" : "=l"(d) : "l"(a), "l"(b), "l"(c)); return d;
}
__device__ __forceinline__ ull pk2(float lo, float hi) {
    ull r; asm("mov.b64 %0,{%1,%2};" : "=l"(r) : "f"(lo), "f"(hi)); return r;
}
__device__ __forceinline__ void upk2(ull v, float& lo, float& hi) {
    asm("mov.b64 {%0,%1},%2;" : "=f"(lo), "=f"(hi) : "l"(v));
}

__device__ __forceinline__ float sigf(float x) {
    return __fdividef(1.0f, 1.0f + __expf(-x));
}
__device__ __forceinline__ float tanh_fast(float x) {
    return __fdividef(2.0f, 1.0f + __expf(-2.0f * x)) - 1.0f;
}

// Shared layout (floats):
//   sW0  : 900 float4  -> [k*30+j] = (wi,wf,wg,wo) of Whh0
//   sWi1 : 900 float4  -> Wih1
//   sWh1 : 900 float4  -> Whh1
//   hb   : WPB warps * 960 floats (layer0: 4 groups * 30 float4 of (h,h,h',h'); layer1 at +480)
#define SMEM_FLOATS (3*900*4 + WPB*960)

__global__ void __launch_bounds__(32*WPB, 1)
stacked_lstm_kernel(const float* __restrict__ x,
                    const float* __restrict__ Wih0, const float* __restrict__ Whh0,
                    const float* __restrict__ bih0, const float* __restrict__ bhh0,
                    const float* __restrict__ Wih1, const float* __restrict__ Whh1,
                    const float* __restrict__ bih1, const float* __restrict__ bhh1,
                    const float* __restrict__ Wfc1, const float* __restrict__ bfc1,
                    const float* __restrict__ Wfc2, const float* __restrict__ bfc2,
                    const float* __restrict__ Wfc3, const float* __restrict__ bfc3,
                    float* __restrict__ out, int B)
{
    extern __shared__ float smem[];
    float4* sW0  = (float4*)smem;
    float4* sWi1 = sW0  + 900;
    float4* sWh1 = sWi1 + 900;
    float*  hbAll = (float*)(sWh1 + 900);

    const int tid = threadIdx.x;
    const int nthr = 32 * WPB;

    // Fill transposed, gate-interleaved weights: src row = g*30+j, col k.
    for (int idx = tid; idx < 3600; idx += nthr) {
        int row = idx / HH, k = idx % HH;
        int g = row / HH, j = row % HH;
        ((float*)&sW0 [k*HH + j])[g] = Whh0[idx];
        ((float*)&sWi1[k*HH + j])[g] = Wih1[idx];
        ((float*)&sWh1[k*HH + j])[g] = Whh1[idx];
    }
    for (int idx = tid; idx < WPB*960; idx += nthr) hbAll[idx] = 0.0f;
    __syncthreads();

    const int wib  = tid >> 5;
    const int lane = tid & 31;
    const int jj   = lane < HH ? lane : HH - 1;   // lanes 30,31 duplicate unit 29
    const int warp = blockIdx.x * WPB + wib;
    const long wb  = (long)warp * NB;
    if (wb >= B) return;

    float* hb = hbAll + wib * 960;
    const ulonglong2* w0p  = (const ulonglong2*)sW0;
    const ulonglong2* wi1p = (const ulonglong2*)sWi1;
    const ulonglong2* wh1p = (const ulonglong2*)sWh1;
    const ulonglong2* hp0  = (const ulonglong2*)hb;        // layer0 h, [g*30+k]
    const ulonglong2* hp1  = hp0 + 120;                    // layer1 h
    float4* st0 = (float4*)hb;
    float4* st1 = (float4*)(hb + 480);

    // Per-lane constants (gate pairs: IF = (i,f), GO = (g,o))
    const ull b0IF = pk2(bih0[jj]      + bhh0[jj],      bih0[jj + 30] + bhh0[jj + 30]);
    const ull b0GO = pk2(bih0[jj + 60] + bhh0[jj + 60], bih0[jj + 90] + bhh0[jj + 90]);
    const ull b1IF = pk2(bih1[jj]      + bhh1[jj],      bih1[jj + 30] + bhh1[jj + 30]);
    const ull b1GO = pk2(bih1[jj + 60] + bhh1[jj + 60], bih1[jj + 90] + bhh1[jj + 90]);
    ull wIF[INP], wGO[INP];
    #pragma unroll
    for (int c = 0; c < INP; c++) {
        wIF[c] = pk2(Wih0[jj*INP + c],        Wih0[(jj+30)*INP + c]);
        wGO[c] = pk2(Wih0[(jj+60)*INP + c],   Wih0[(jj+90)*INP + c]);
    }

    float c0v[NB], c1v[NB], h1s[NB];
    #pragma unroll
    for (int e = 0; e < NB; e++) { c0v[e] = 0.f; c1v[e] = 0.f; h1s[e] = 0.f; }

    const float* xbase = x + (size_t)wb * TT * INP;
    ull aIF[NB], aGO[NB];

    // Prefetch x[t=0]
    float xv[NB][INP];
    #pragma unroll
    for (int e = 0; e < NB; e++) {
        const float* xp = xbase + (size_t)e * TT * INP;
        xv[e][0] = xp[0]; xv[e][1] = xp[1]; xv[e][2] = xp[2];
    }

    for (int t = 0; t < TT; t++) {
        // consume current x into gate accumulators immediately
        #pragma unroll
        for (int e = 0; e < NB; e++) {
            ull d0 = pk2(xv[e][0], xv[e][0]);
            ull d1 = pk2(xv[e][1], xv[e][1]);
            ull d2 = pk2(xv[e][2], xv[e][2]);
            aIF[e] = fma2(wIF[0], d0, fma2(wIF[1], d1, fma2(wIF[2], d2, b0IF)));
            aGO[e] = fma2(wGO[0], d0, fma2(wGO[1], d1, fma2(wGO[2], d2, b0GO)));
        }

        // prefetch next timestep's x (LDG latency hidden behind the k-loops)
        if (t + 1 < TT) {
            #pragma unroll
            for (int e = 0; e < NB; e++) {
                const float* xp = xbase + ((size_t)e * TT + (t + 1)) * INP;
                xv[e][0] = xp[0]; xv[e][1] = xp[1]; xv[e][2] = xp[2];
            }
        }

        // ---- layer 0: gates += Whh0 * h0 ----
        #pragma unroll
        for (int k = 0; k < HH; k++) {
            ulonglong2 w  = w0p[k*HH + jj];
            ulonglong2 hA = hp0[k], hB = hp0[30 + k], hC = hp0[60 + k], hD = hp0[90 + k];
            aIF[0] = fma2(w.x, hA.x, aIF[0]); aGO[0] = fma2(w.y, hA.x, aGO[0]);
            aIF[1] = fma2(w.x, hA.y, aIF[1]); aGO[1] = fma2(w.y, hA.y, aGO[1]);
            aIF[2] = fma2(w.x, hB.x, aIF[2]); aGO[2] = fma2(w.y, hB.x, aGO[2]);
            aIF[3] = fma2(w.x, hB.y, aIF[3]); aGO[3] = fma2(w.y, hB.y, aGO[3]);
            aIF[4] = fma2(w.x, hC.x, aIF[4]); aGO[4] = fma2(w.y, hC.x, aGO[4]);
            aIF[5] = fma2(w.x, hC.y, aIF[5]); aGO[5] = fma2(w.y, hC.y, aGO[5]);
            aIF[6] = fma2(w.x, hD.x, aIF[6]); aGO[6] = fma2(w.y, hD.x, aGO[6]);
            aIF[7] = fma2(w.x, hD.y, aIF[7]); aGO[7] = fma2(w.y, hD.y, aGO[7]);
        }

        float h0n[NB];
        #pragma unroll
        for (int e = 0; e < NB; e++) {
            float ui, uf, ug, uo;
            upk2(aIF[e], ui, uf); upk2(aGO[e], ug, uo);
            float ig = sigf(ui), fg = sigf(uf), gg = tanh_fast(ug), og = sigf(uo);
            float c = fmaf(fg, c0v[e], ig * gg);
            c0v[e] = c;
            h0n[e] = og * tanh_fast(c);
        }
        if (lane < HH) {
            st0[jj]      = make_float4(h0n[0], h0n[0], h0n[1], h0n[1]);
            st0[30 + jj] = make_float4(h0n[2], h0n[2], h0n[3], h0n[3]);
            st0[60 + jj] = make_float4(h0n[4], h0n[4], h0n[5], h0n[5]);
            st0[90 + jj] = make_float4(h0n[6], h0n[6], h0n[7], h0n[7]);
        }
        __syncwarp();

        // ---- layer 1: gates = b1 + Wih1*h0 + Whh1*h1 ----
        #pragma unroll
        for (int e = 0; e < NB; e++) { aIF[e] = b1IF; aGO[e] = b1GO; }
        #pragma unroll
        for (int k = 0; k < HH; k++) {
            ulonglong2 wi = wi1p[k*HH + jj];
            ulonglong2 wh = wh1p[k*HH + jj];
            ulonglong2 hA = hp0[k], hB = hp0[30 + k], hC = hp0[60 + k], hD = hp0[90 + k];
            ulonglong2 gA = hp1[k], gB = hp1[30 + k], gC = hp1[60 + k], gD = hp1[90 + k];
            aIF[0] = fma2(wi.x, hA.x, fma2(wh.x, gA.x, aIF[0]));
            aGO[0] = fma2(wi.y, hA.x, fma2(wh.y, gA.x, aGO[0]));
            aIF[1] = fma2(wi.x, hA.y, fma2(wh.x, gA.y, aIF[1]));
            aGO[1] = fma2(wi.y, hA.y, fma2(wh.y, gA.y, aGO[1]));
            aIF[2] = fma2(wi.x, hB.x, fma2(wh.x, gB.x, aIF[2]));
            aGO[2] = fma2(wi.y, hB.x, fma2(wh.y, gB.x, aGO[2]));
            aIF[3] = fma2(wi.x, hB.y, fma2(wh.x, gB.y, aIF[3]));
            aGO[3] = fma2(wi.y, hB.y, fma2(wh.y, gB.y, aGO[3]));
            aIF[4] = fma2(wi.x, hC.x, fma2(wh.x, gC.x, aIF[4]));
            aGO[4] = fma2(wi.y, hC.x, fma2(wh.y, gC.x, aGO[4]));
            aIF[5] = fma2(wi.x, hC.y, fma2(wh.x, gC.y, aIF[5]));
            aGO[5] = fma2(wi.y, hC.y, fma2(wh.y, gC.y, aGO[5]));
            aIF[6] = fma2(wi.x, hD.x, fma2(wh.x, gD.x, aIF[6]));
            aGO[6] = fma2(wi.y, hD.x, fma2(wh.y, gD.x, aGO[6]));
            aIF[7] = fma2(wi.x, hD.y, fma2(wh.x, gD.y, aIF[7]));
            aGO[7] = fma2(wi.y, hD.y, fma2(wh.y, gD.y, aGO[7]));
        }

        float h1n[NB];
        #pragma unroll
        for (int e = 0; e < NB; e++) {
            float ui, uf, ug, uo;
            upk2(aIF[e], ui, uf); upk2(aGO[e], ug, uo);
            float ig = sigf(ui), fg = sigf(uf), gg = tanh_fast(ug), og = sigf(uo);
            float c = fmaf(fg, c1v[e], ig * gg);
            c1v[e] = c;
            h1n[e] = og * tanh_fast(c);
            h1s[e] = h1n[e];
        }
        if (lane < HH) {
            st1[jj]      = make_float4(h1n[0], h1n[0], h1n[1], h1n[1]);
            st1[30 + jj] = make_float4(h1n[2], h1n[2], h1n[3], h1n[3]);
            st1[60 + jj] = make_float4(h1n[4], h1n[4], h1n[5], h1n[5]);
            st1[90 + jj] = make_float4(h1n[6], h1n[6], h1n[7], h1n[7]);
        }
        __syncwarp();
    }

    // ---------------- FC head (per warp, shuffles; one-time cost) ----------------
    const unsigned FULL = 0xffffffffu;
    float za[NB], zb[NB];
    #pragma unroll
    for (int e = 0; e < NB; e++) { za[e] = bfc1[lane]; zb[e] = bfc1[lane + 32]; }
    for (int k = 0; k < HH; k++) {
        float wa = Wfc1[lane * HH + k];
        float wbv = Wfc1[(lane + 32) * HH + k];
        #pragma unroll
        for (int e = 0; e < NB; e++) {
            float hk = __shfl_sync(FULL, h1s[e], k);
            za[e] = fmaf(wa, hk, za[e]);
            zb[e] = fmaf(wbv, hk, zb[e]);
        }
    }
    #pragma unroll
    for (int e = 0; e < NB; e++) { za[e] = fmaxf(za[e], 0.f); zb[e] = fmaxf(zb[e], 0.f); }

    float z2[NB];
    #pragma unroll
    for (int e = 0; e < NB; e++) z2[e] = bfc2[lane];
    for (int k = 0; k < 32; k++) {
        float w1 = Wfc2[lane * 64 + k];
        float w2 = Wfc2[lane * 64 + 32 + k];
        #pragma unroll
        for (int e = 0; e < NB; e++) {
            float zak = __shfl_sync(FULL, za[e], k);
            float zbk = __shfl_sync(FULL, zb[e], k);
            z2[e] = fmaf(w1, zak, fmaf(w2, zbk, z2[e]));
        }
    }
    float w3 = Wfc3[lane];
    float b3 = bfc3[0];
    #pragma unroll
    for (int e = 0; e < NB; e++) {
        float p = w3 * fmaxf(z2[e], 0.f);
        #pragma unroll
        for (int off = 16; off; off >>= 1) p += __shfl_xor_sync(FULL, p, off);
        if (lane == 0) out[wb + e] = sigf(p + b3);
    }
}

extern "C" void kernel_launch(void* const* d_in, const int* in_sizes, int n_in,
                              void* d_out, int out_size)
{
    const float* x    = (const float*)d_in[0];
    const float* Wih0 = (const float*)d_in[1];
    const float* Whh0 = (const float*)d_in[2];
    const float* bih0 = (const float*)d_in[3];
    const float* bhh0 = (const float*)d_in[4];
    const float* Wih1 = (const float*)d_in[5];
    const float* Whh1 = (const float*)d_in[6];
    const float* bih1 = (const float*)d_in[7];
    const float* bhh1 = (const float*)d_in[8];
    const float* Wfc1 = (const float*)d_in[9];
    const float* bfc1 = (const float*)d_in[10];
    const float* Wfc2 = (const float*)d_in[11];
    const float* bfc2 = (const float*)d_in[12];
    const float* Wfc3 = (const float*)d_in[13];
    const float* bfc3 = (const float*)d_in[14];
    float* out = (float*)d_out;

    int B = in_sizes[0] / (TT * INP);                 // 8192
    int warps = (B + NB - 1) / NB;                    // 1024
    int blocks = (warps + WPB - 1) / WPB;             // 147 -> one balanced wave on 148 SMs

    size_t smem_bytes = SMEM_FLOATS * sizeof(float);  // ~70.1 KB
    cudaFuncSetAttribute(stacked_lstm_kernel,
                         cudaFuncAttributeMaxDynamicSharedMemorySize,
                         (int)smem_bytes);

    stacked_lstm_kernel<<<blocks, 32*WPB, smem_bytes>>>(x,
        Wih0, Whh0, bih0, bhh0,
        Wih1, Whh1, bih1, bhh1,
        Wfc1, bfc1, Wfc2, bfc2, Wfc3, bfc3,
        out, B);
}

// round 4
// speedup vs baseline: 1.0786x; 1.0786x over previous
#include <cuda_runtime.h>

#define TT   256
#define HH   30
#define INP  3
#define NB   4            // batch elements per warp
#define WPB  4            // warps per block (128 threads)

typedef unsigned long long ull;

// ---- f32x2 packed helpers (sm_103a) ----
__device__ __forceinline__ ull fma2(ull a, ull b, ull c) {
    ull d; asm("fma.rn.f32x2 %0,%1,%2,%3;" : "=l"(d) : "l"(a), "l"(b), "l"(c)); return d;
}
__device__ __forceinline__ ull pk2(float lo, float hi) {
    ull r; asm("mov.b64 %0,{%1,%2};" : "=l"(r) : "f"(lo), "f"(hi)); return r;
}
__device__ __forceinline__ void upk2(ull v, float& lo, float& hi) {
    asm("mov.b64 {%0,%1},%2;" : "=f"(lo), "=f"(hi) : "l"(v));
}

__device__ __forceinline__ float sigf(float x) {
    return __fdividef(1.0f, 1.0f + __expf(-x));
}
__device__ __forceinline__ float tanh_fast(float x) {
    return __fdividef(2.0f, 1.0f + __expf(-2.0f * x)) - 1.0f;
}

// Shared layout (floats):
//   sW0  : 900 float4  -> [k*30+j] = (wi,wf,wg,wo) of Whh0
//   sWi1 : 900 float4  -> Wih1
//   sWh1 : 900 float4  -> Whh1
//   hb   : WPB warps * 480 floats
//          layer0: 2 groups * 30 float4  [g*30+k] = (h_{2g},h_{2g},h_{2g+1},h_{2g+1})
//          layer1: same, at +240 floats
#define SMEM_FLOATS (3*900*4 + WPB*480)

__global__ void __launch_bounds__(32*WPB)
stacked_lstm_kernel(const float* __restrict__ x,
                    const float* __restrict__ Wih0, const float* __restrict__ Whh0,
                    const float* __restrict__ bih0, const float* __restrict__ bhh0,
                    const float* __restrict__ Wih1, const float* __restrict__ Whh1,
                    const float* __restrict__ bih1, const float* __restrict__ bhh1,
                    const float* __restrict__ Wfc1, const float* __restrict__ bfc1,
                    const float* __restrict__ Wfc2, const float* __restrict__ bfc2,
                    const float* __restrict__ Wfc3, const float* __restrict__ bfc3,
                    float* __restrict__ out, int B)
{
    extern __shared__ float smem[];
    float4* sW0  = (float4*)smem;
    float4* sWi1 = sW0  + 900;
    float4* sWh1 = sWi1 + 900;
    float*  hbAll = (float*)(sWh1 + 900);

    const int tid = threadIdx.x;
    const int nthr = 32 * WPB;

    // Fill transposed, gate-interleaved weights: src row = g*30+j, col k.
    for (int idx = tid; idx < 3600; idx += nthr) {
        int row = idx / HH, k = idx % HH;
        int g = row / HH, j = row % HH;
        ((float*)&sW0 [k*HH + j])[g] = Whh0[idx];
        ((float*)&sWi1[k*HH + j])[g] = Wih1[idx];
        ((float*)&sWh1[k*HH + j])[g] = Whh1[idx];
    }
    for (int idx = tid; idx < WPB*480; idx += nthr) hbAll[idx] = 0.0f;
    __syncthreads();

    const int wib  = tid >> 5;
    const int lane = tid & 31;
    const int jj   = lane < HH ? lane : HH - 1;   // lanes 30,31 duplicate unit 29
    const int warp = blockIdx.x * WPB + wib;
    const long wb  = (long)warp * NB;
    if (wb >= B) return;

    float* hb = hbAll + wib * 480;
    const ulonglong2* w0p  = (const ulonglong2*)sW0;
    const ulonglong2* wi1p = (const ulonglong2*)sWi1;
    const ulonglong2* wh1p = (const ulonglong2*)sWh1;
    const ulonglong2* hp0  = (const ulonglong2*)hb;        // layer0 h, [g*30+k]
    const ulonglong2* hp1  = hp0 + 60;                     // layer1 h
    float4* st0 = (float4*)hb;
    float4* st1 = (float4*)(hb + 240);

    // Per-lane constants (gate pairs: IF = (i,f), GO = (g,o))
    const ull b0IF = pk2(bih0[jj]      + bhh0[jj],      bih0[jj + 30] + bhh0[jj + 30]);
    const ull b0GO = pk2(bih0[jj + 60] + bhh0[jj + 60], bih0[jj + 90] + bhh0[jj + 90]);
    const ull b1IF = pk2(bih1[jj]      + bhh1[jj],      bih1[jj + 30] + bhh1[jj + 30]);
    const ull b1GO = pk2(bih1[jj + 60] + bhh1[jj + 60], bih1[jj + 90] + bhh1[jj + 90]);
    ull wIF[INP], wGO[INP];
    #pragma unroll
    for (int c = 0; c < INP; c++) {
        wIF[c] = pk2(Wih0[jj*INP + c],        Wih0[(jj+30)*INP + c]);
        wGO[c] = pk2(Wih0[(jj+60)*INP + c],   Wih0[(jj+90)*INP + c]);
    }

    float c0v[NB], c1v[NB], h1s[NB];
    #pragma unroll
    for (int e = 0; e < NB; e++) { c0v[e] = 0.f; c1v[e] = 0.f; h1s[e] = 0.f; }

    const float* xbase = x + (size_t)wb * TT * INP;
    ull aIF[NB], aGO[NB];

    for (int t = 0; t < TT; t++) {
        // ---- x contribution ----
        #pragma unroll
        for (int e = 0; e < NB; e++) {
            const float* xp = xbase + ((size_t)e * TT + t) * INP;
            float x0 = xp[0], x1 = xp[1], x2 = xp[2];
            ull d0 = pk2(x0, x0);
            ull d1 = pk2(x1, x1);
            ull d2 = pk2(x2, x2);
            aIF[e] = fma2(wIF[0], d0, fma2(wIF[1], d1, fma2(wIF[2], d2, b0IF)));
            aGO[e] = fma2(wGO[0], d0, fma2(wGO[1], d1, fma2(wGO[2], d2, b0GO)));
        }

        // ---- layer 0: gates += Whh0 * h0 ----
        #pragma unroll
        for (int k = 0; k < HH; k++) {
            ulonglong2 w  = w0p[k*HH + jj];
            ulonglong2 hA = hp0[k], hB = hp0[30 + k];
            aIF[0] = fma2(w.x, hA.x, aIF[0]); aGO[0] = fma2(w.y, hA.x, aGO[0]);
            aIF[1] = fma2(w.x, hA.y, aIF[1]); aGO[1] = fma2(w.y, hA.y, aGO[1]);
            aIF[2] = fma2(w.x, hB.x, aIF[2]); aGO[2] = fma2(w.y, hB.x, aGO[2]);
            aIF[3] = fma2(w.x, hB.y, aIF[3]); aGO[3] = fma2(w.y, hB.y, aGO[3]);
        }

        float h0n[NB];
        #pragma unroll
        for (int e = 0; e < NB; e++) {
            float ui, uf, ug, uo;
            upk2(aIF[e], ui, uf); upk2(aGO[e], ug, uo);
            float ig = sigf(ui), fg = sigf(uf), gg = tanh_fast(ug), og = sigf(uo);
            float c = fmaf(fg, c0v[e], ig * gg);
            c0v[e] = c;
            h0n[e] = og * tanh_fast(c);
        }
        if (lane < HH) {
            st0[jj]      = make_float4(h0n[0], h0n[0], h0n[1], h0n[1]);
            st0[30 + jj] = make_float4(h0n[2], h0n[2], h0n[3], h0n[3]);
        }
        __syncwarp();

        // ---- layer 1: gates = b1 + Wih1*h0 + Whh1*h1 ----
        #pragma unroll
        for (int e = 0; e < NB; e++) { aIF[e] = b1IF; aGO[e] = b1GO; }
        #pragma unroll
        for (int k = 0; k < HH; k++) {
            ulonglong2 wi = wi1p[k*HH + jj];
            ulonglong2 wh = wh1p[k*HH + jj];
            ulonglong2 hA = hp0[k], hB = hp0[30 + k];
            ulonglong2 gA = hp1[k], gB = hp1[30 + k];
            aIF[0] = fma2(wi.x, hA.x, fma2(wh.x, gA.x, aIF[0]));
            aGO[0] = fma2(wi.y, hA.x, fma2(wh.y, gA.x, aGO[0]));
            aIF[1] = fma2(wi.x, hA.y, fma2(wh.x, gA.y, aIF[1]));
            aGO[1] = fma2(wi.y, hA.y, fma2(wh.y, gA.y, aGO[1]));
            aIF[2] = fma2(wi.x, hB.x, fma2(wh.x, gB.x, aIF[2]));
            aGO[2] = fma2(wi.y, hB.x, fma2(wh.y, gB.x, aGO[2]));
            aIF[3] = fma2(wi.x, hB.y, fma2(wh.x, gB.y, aIF[3]));
            aGO[3] = fma2(wi.y, hB.y, fma2(wh.y, gB.y, aGO[3]));
        }

        float h1n[NB];
        #pragma unroll
        for (int e = 0; e < NB; e++) {
            float ui, uf, ug, uo;
            upk2(aIF[e], ui, uf); upk2(aGO[e], ug, uo);
            float ig = sigf(ui), fg = sigf(uf), gg = tanh_fast(ug), og = sigf(uo);
            float c = fmaf(fg, c1v[e], ig * gg);
            c1v[e] = c;
            h1n[e] = og * tanh_fast(c);
            h1s[e] = h1n[e];
        }
        if (lane < HH) {
            st1[jj]      = make_float4(h1n[0], h1n[0], h1n[1], h1n[1]);
            st1[30 + jj] = make_float4(h1n[2], h1n[2], h1n[3], h1n[3]);
        }
        __syncwarp();
    }

    // ---------------- FC head (per warp, shuffles; one-time cost) ----------------
    const unsigned FULL = 0xffffffffu;
    float za[NB], zb[NB];
    #pragma unroll
    for (int e = 0; e < NB; e++) { za[e] = bfc1[lane]; zb[e] = bfc1[lane + 32]; }
    for (int k = 0; k < HH; k++) {
        float wa = Wfc1[lane * HH + k];
        float wbv = Wfc1[(lane + 32) * HH + k];
        #pragma unroll
        for (int e = 0; e < NB; e++) {
            float hk = __shfl_sync(FULL, h1s[e], k);
            za[e] = fmaf(wa, hk, za[e]);
            zb[e] = fmaf(wbv, hk, zb[e]);
        }
    }
    #pragma unroll
    for (int e = 0; e < NB; e++) { za[e] = fmaxf(za[e], 0.f); zb[e] = fmaxf(zb[e], 0.f); }

    float z2[NB];
    #pragma unroll
    for (int e = 0; e < NB; e++) z2[e] = bfc2[lane];
    for (int k = 0; k < 32; k++) {
        float w1 = Wfc2[lane * 64 + k];
        float w2 = Wfc2[lane * 64 + 32 + k];
        #pragma unroll
        for (int e = 0; e < NB; e++) {
            float zak = __shfl_sync(FULL, za[e], k);
            float zbk = __shfl_sync(FULL, zb[e], k);
            z2[e] = fmaf(w1, zak, fmaf(w2, zbk, z2[e]));
        }
    }
    float w3 = Wfc3[lane];
    float b3 = bfc3[0];
    #pragma unroll
    for (int e = 0; e < NB; e++) {
        float p = w3 * fmaxf(z2[e], 0.f);
        #pragma unroll
        for (int off = 16; off; off >>= 1) p += __shfl_xor_sync(FULL, p, off);
        if (lane == 0) out[wb + e] = sigf(p + b3);
    }
}

extern "C" void kernel_launch(void* const* d_in, const int* in_sizes, int n_in,
                              void* d_out, int out_size)
{
    const float* x    = (const float*)d_in[0];
    const float* Wih0 = (const float*)d_in[1];
    const float* Whh0 = (const float*)d_in[2];
    const float* bih0 = (const float*)d_in[3];
    const float* bhh0 = (const float*)d_in[4];
    const float* Wih1 = (const float*)d_in[5];
    const float* Whh1 = (const float*)d_in[6];
    const float* bih1 = (const float*)d_in[7];
    const float* bhh1 = (const float*)d_in[8];
    const float* Wfc1 = (const float*)d_in[9];
    const float* bfc1 = (const float*)d_in[10];
    const float* Wfc2 = (const float*)d_in[11];
    const float* bfc2 = (const float*)d_in[12];
    const float* Wfc3 = (const float*)d_in[13];
    const float* bfc3 = (const float*)d_in[14];
    float* out = (float*)d_out;

    int B = in_sizes[0] / (TT * INP);                 // 8192
    int warps = (B + NB - 1) / NB;                    // 2048
    int blocks = (warps + WPB - 1) / WPB;             // 512

    size_t smem_bytes = SMEM_FLOATS * sizeof(float);  // ~50.9 KB
    cudaFuncSetAttribute(stacked_lstm_kernel,
                         cudaFuncAttributeMaxDynamicSharedMemorySize,
                         (int)smem_bytes);

    stacked_lstm_kernel<<<blocks, 32*WPB, smem_bytes>>>(x,
        Wih0, Whh0, bih0, bhh0,
        Wih1, Whh1, bih1, bhh1,
        Wfc1, bfc1, Wfc2, bfc2, Wfc3, bfc3,
        out, B);
}